// round 15
// baseline (speedup 1.0000x reference)
#include <cuda_runtime.h>

#define N_GAUSS 3200
#define FEAT    17
#define FV4     5             // padded feature float4 count (20 floats)
#define RH      48
#define RW      88
#define NPIX    (RH*RW)       // 4224
#define NPAIR   (NPIX/2)      // 2112
#define NCAM    2
#define GH      192
#define GW      352
#define NSEG    25
#define SEGSZ   128           // 25*128 = 3200
#define KCH     4
#define KLEN    (N_GAUSS/KCH) // 800
#define RTILES  33            // NPAIR/64 render tiling (2 px/thread, 64-thread CTAs)
#define RBLK    64
#define NPAIRCH 9             // (FEAT+1)/2 feature-channel pairs
#define PPW     20            // packed floats per (seg,pixel): 17 logits + T + pad
#define LTILE   32            // pixels per loss CTA
#define LGROUPS 16            // segment groups per loss CTA
#define LBLOCKS (NPIX/LTILE)  // 132 loss CTAs per camera

// -------- device scratch (static: allocation-free) --------
__device__ int    d_rankp[KCH][NCAM*N_GAUSS];  // per-chunk partial ranks (no atomics)
__device__ float4 d_sp0[NCAM*N_GAUSS];   // sorted (v, E, u, op)
__device__ float4 d_sp1[NCAM*N_GAUSS];   // sorted (A, B, C, 0)
__device__ float4 d_sf4[NCAM*NSEG*FV4*SEGSZ]; // sorted feats, seg-blocked
__device__ float  d_segP[NCAM*NSEG*NPIX*PPW]; // packed per-(seg,pixel): 17 logits + T
__device__ float  d_num[NCAM];
__device__ float  d_den[NCAM];
__device__ unsigned int d_ctr;

// deterministic z: explicit fma chain — identical rounding at every call site
__device__ __forceinline__ float zdet(const float* __restrict__ xyz, int k,
                                      float V8, float V9, float V10, float V11)
{
    return __fmaf_rn(V8, xyz[3*k], __fmaf_rn(V9, xyz[3*k+1], __fmaf_rn(V10, xyz[3*k+2], V11)));
}

// -------- 1) stable rank via tiled O(N^2) counting, z computed on the fly --------
__global__ void k_rank(const float* __restrict__ xyz, const float* __restrict__ vm)
{
    int cam = blockIdx.z;
    int ch  = blockIdx.y;
    int n   = blockIdx.x * 256 + threadIdx.x;
    int base = ch * KLEN;
    if (cam == 0 && ch == 0 && blockIdx.x == 0 && threadIdx.x < NCAM) {
        d_num[threadIdx.x] = 0.f; d_den[threadIdx.x] = 0.f;
        if (threadIdx.x == 0) d_ctr = 0u;
    }
    const float* V = vm + cam*16;
    float V8 = V[8], V9 = V[9], V10 = V[10], V11 = V[11];

    __shared__ float tz[256];
    float zn = (n < N_GAUSS) ? zdet(xyz, n, V8, V9, V10, V11) : 0.f;
    int cnt = 0;
    for (int t0 = 0; t0 < KLEN; t0 += 256) {
        int lim = KLEN - t0 < 256 ? KLEN - t0 : 256;
        __syncthreads();
        if (threadIdx.x < lim) tz[threadIdx.x] = zdet(xyz, base + t0 + threadIdx.x, V8, V9, V10, V11);
        __syncthreads();
        if (n < N_GAUSS) {
            for (int j = 0; j < lim; j++) {
                float zm = tz[j];
                int mm = base + t0 + j;
                cnt += (zm < zn) || (zm == zn && mm < n);
            }
        }
    }
    if (n < N_GAUSS) d_rankp[ch][cam*N_GAUSS + n] = cnt;
}

// -------- 2) fused projection (R1 math) + scatter to sorted slots --------
__global__ void k_ps(const float* __restrict__ xyz, const float* __restrict__ scales,
                     const float* __restrict__ rots, const float* __restrict__ opac,
                     const float* __restrict__ vm, const float* __restrict__ intr,
                     const float* __restrict__ feats)
{
    int n = blockIdx.x * 256 + threadIdx.x;
    int cam = blockIdx.y;
    if (n >= N_GAUSS) return;
    int gi = cam*N_GAUSS + n;
    int rank = d_rankp[0][gi] + d_rankp[1][gi] + d_rankp[2][gi] + d_rankp[3][gi];

    const float* V = vm + cam*16;
    float fx = intr[cam*4+0], fy = intr[cam*4+1], cx = intr[cam*4+2], cy = intr[cam*4+3];
    float X = xyz[3*n], Y = xyz[3*n+1], Z = xyz[3*n+2];
    float p0 = V[0]*X + V[1]*Y + V[2] *Z + V[3];
    float p1 = V[4]*X + V[5]*Y + V[6] *Z + V[7];
    float p2 = V[8]*X + V[9]*Y + V[10]*Z + V[11];
    float z  = p2;
    float zc = fmaxf(z, 0.2f);
    float iz = 1.0f / zc;
    float u  = fx*p0*iz + cx;
    float v  = fy*p1*iz + cy;

    float qw = rots[4*n], qx = rots[4*n+1], qy = rots[4*n+2], qz = rots[4*n+3];
    float qn = rsqrtf(qw*qw + qx*qx + qy*qy + qz*qz);
    qw *= qn; qx *= qn; qy *= qn; qz *= qn;
    float R00 = 1.f-2.f*(qy*qy+qz*qz), R01 = 2.f*(qx*qy-qw*qz), R02 = 2.f*(qx*qz+qw*qy);
    float R10 = 2.f*(qx*qy+qw*qz),     R11 = 1.f-2.f*(qx*qx+qz*qz), R12 = 2.f*(qy*qz-qw*qx);
    float R20 = 2.f*(qx*qz-qw*qy),     R21 = 2.f*(qy*qz+qw*qx), R22 = 1.f-2.f*(qx*qx+qy*qy);

    float s0 = __expf(scales[3*n]), s1 = __expf(scales[3*n+1]), s2 = __expf(scales[3*n+2]);
    float e0 = s0*s0, e1 = s1*s1, e2 = s2*s2;

    float M00 = R00*R00*e0 + R01*R01*e1 + R02*R02*e2;
    float M01 = R00*R10*e0 + R01*R11*e1 + R02*R12*e2;
    float M02 = R00*R20*e0 + R01*R21*e1 + R02*R22*e2;
    float M11 = R10*R10*e0 + R11*R11*e1 + R12*R12*e2;
    float M12 = R10*R20*e0 + R11*R21*e1 + R12*R22*e2;
    float M22 = R20*R20*e0 + R21*R21*e1 + R22*R22*e2;

    float W00=V[0],W01=V[1],W02=V[2];
    float W10=V[4],W11=V[5],W12=V[6];
    float W20=V[8],W21=V[9],W22=V[10];
    float T00=W00*M00+W01*M01+W02*M02, T01=W00*M01+W01*M11+W02*M12, T02=W00*M02+W01*M12+W02*M22;
    float T10=W10*M00+W11*M01+W12*M02, T11=W10*M01+W11*M11+W12*M12, T12=W10*M02+W11*M12+W12*M22;
    float T20=W20*M00+W21*M01+W22*M02, T21=W20*M01+W21*M11+W22*M12, T22=W20*M02+W21*M12+W22*M22;
    float C00=T00*W00+T01*W01+T02*W02;
    float C01=T00*W10+T01*W11+T02*W12;
    float C02=T00*W20+T01*W21+T02*W22;
    float C11=T10*W10+T11*W11+T12*W12;
    float C12=T10*W20+T11*W21+T12*W22;
    float C22=T20*W20+T21*W21+T22*W22;

    float fz0 = fx*iz, fz1 = fy*iz;
    float g0 = -fx*p0*iz*iz, g1 = -fy*p1*iz*iz;
    float t0x = C00*fz0 + C02*g0;
    float t0y = C01*fz0 + C12*g0;
    float t0z = C02*fz0 + C22*g0;
    float cov00 = fz0*t0x + g0*t0z;
    float cov01 = fz1*t0y + g1*t0z;
    float t1y = C11*fz1 + C12*g1;
    float t1z = C12*fz1 + C22*g1;
    float cov11 = fz1*t1y + g1*t1z;

    float a = cov00 + 0.3f;
    float b = cov01;
    float c = cov11 + 0.3f;
    float det  = fmaxf(a*c - b*b, 1e-8f);
    float idet = 1.0f / det;

    float oz = (z > 0.2f) ? opac[n] : 0.0f;

    float Ax = c*idet;       // dx^2 coefficient (R1 value)
    float By = -b*idet;      // cross coefficient (R1 value)
    float Cy = a*idet;       // dy^2 coefficient (R1 value)
    float E  = Cy - By*By/Ax;  // 1D marginal coeff: min over dx of -2*pw = E*dy^2

    int pos = cam*N_GAUSS + rank;
    d_sp0[pos] = make_float4(v, E, u, oz);
    d_sp1[pos] = make_float4(Ax, By, Cy, 0.f);

    int seg = rank / SEGSZ, t = rank % SEGSZ;
    const float* f = feats + n*FEAT;
    float fv[FV4*4];
#pragma unroll
    for (int cc = 0; cc < FEAT; cc++) fv[cc] = f[cc];
#pragma unroll
    for (int cc = FEAT; cc < FV4*4; cc++) fv[cc] = 0.f;
    float4* dst = &d_sf4[((cam*NSEG + seg)*FV4)*SEGSZ + t];
#pragma unroll
    for (int j = 0; j < FV4; j++)
        dst[j*SEGSZ] = make_float4(fv[4*j], fv[4*j+1], fv[4*j+2], fv[4*j+3]);
}

// -------- 3) segmented compositing: 2 px/thread + FFMA2 + dy early-out --------
__global__ void __launch_bounds__(RBLK) k_render()
{
    int seg  = blockIdx.x;
    int tile = blockIdx.y;
    int cam  = blockIdx.z;
    __shared__ float4 sve[SEGSZ];              // (v, E, u, op)
    __shared__ float4 sab[SEGSZ];              // (A, B, C, 0)
    __shared__ ulonglong2 sfp[NPAIRCH*SEGSZ];  // features duplicated as (f,f) pairs
    int t = threadIdx.x;
#pragma unroll
    for (int tt = t; tt < SEGSZ; tt += RBLK) {
        int g = cam*N_GAUSS + seg*SEGSZ + tt;
        sve[tt] = d_sp0[g];
        sab[tt] = d_sp1[g];
        const float4* src = &d_sf4[((cam*NSEG + seg)*FV4)*SEGSZ + tt];
        float f[FV4*4];
#pragma unroll
        for (int j = 0; j < FV4; j++) {
            float4 q = src[j*SEGSZ];
            f[4*j] = q.x; f[4*j+1] = q.y; f[4*j+2] = q.z; f[4*j+3] = q.w;
        }
#pragma unroll
        for (int j = 0; j < NPAIRCH; j++) {
            ulonglong2 e;
            asm("mov.b64 %0, {%1, %1};" : "=l"(e.x) : "f"(f[2*j]));
            asm("mov.b64 %0, {%1, %1};" : "=l"(e.y) : "f"(f[2*j+1]));
            sfp[j*SEGSZ + tt] = e;
        }
    }
    __syncthreads();

    int pairIdx = tile*RBLK + t;
    int p0 = pairIdx * 2;
    float px0 = (float)(p0 % RW);
    float px1 = px0 + 1.0f;
    float py  = (float)(p0 / RW);
    float T0 = 1.0f, T1 = 1.0f;
    unsigned long long acc2[FEAT+1];
#pragma unroll
    for (int c = 0; c < FEAT+1; c++) acc2[c] = 0ull;

    for (int i = 0; i < SEGSZ; i++) {
        float4 VE = sve[i];            // v, E, u, op
        float dy = py - VE.x;
        // conservative bound: for ALL dx, -pw >= 0.5*E*dy^2. If that exceeds
        // 20.5 > 20, the existing pw > -20 test would fail for every pixel
        // in this row -> skip with zero numeric change. E<0 (det clamp) falls through.
        if (0.5f*VE.y*dy*dy <= 20.5f) {
            float4 Q = sab[i];         // A, B, C
            float dx0 = px0 - VE.z;
            float dx1 = px1 - VE.z;
            float pw0 = -0.5f*(Q.x*dx0*dx0 + Q.z*dy*dy) - Q.y*dx0*dy;  // R1 expression
            float pw1 = -0.5f*(Q.x*dx1*dx1 + Q.z*dy*dy) - Q.y*dx1*dy;
            pw0 = fminf(pw0, 0.0f);
            pw1 = fminf(pw1, 0.0f);
            bool s0 = pw0 > -20.0f;
            bool s1 = pw1 > -20.0f;
            if (s0 | s1) {
                float a0 = fminf(VE.w * __expf(pw0), 0.99f);
                float a1 = fminf(VE.w * __expf(pw1), 0.99f);
                float w0 = s0 ? a0 * T0 : 0.0f;
                float w1 = s1 ? a1 * T1 : 0.0f;
                unsigned long long W;
                asm("mov.b64 %0, {%1, %2};" : "=l"(W) : "f"(w0), "f"(w1));
#pragma unroll
                for (int j = 0; j < NPAIRCH; j++) {
                    ulonglong2 v = sfp[j*SEGSZ + i];
                    asm("fma.rn.f32x2 %0, %1, %2, %0;" : "+l"(acc2[2*j])   : "l"(W), "l"(v.x));
                    asm("fma.rn.f32x2 %0, %1, %2, %0;" : "+l"(acc2[2*j+1]) : "l"(W), "l"(v.y));
                }
                if (s0) T0 *= 1.0f - a0;
                if (s1) T1 *= 1.0f - a1;
            }
        }
    }
    {
        int idx = cam*NSEG + seg;
        float lo[FEAT], hi[FEAT];
#pragma unroll
        for (int c = 0; c < FEAT; c++)
            asm("mov.b64 {%0, %1}, %2;" : "=f"(lo[c]), "=f"(hi[c]) : "l"(acc2[c]));
        float4* o0 = (float4*)&d_segP[(idx*NPIX + p0) * PPW];
        o0[0] = make_float4(lo[0],  lo[1],  lo[2],  lo[3]);
        o0[1] = make_float4(lo[4],  lo[5],  lo[6],  lo[7]);
        o0[2] = make_float4(lo[8],  lo[9],  lo[10], lo[11]);
        o0[3] = make_float4(lo[12], lo[13], lo[14], lo[15]);
        o0[4] = make_float4(lo[16], T0, 0.f, 0.f);
        float4* o1 = (float4*)&d_segP[(idx*NPIX + p0 + 1) * PPW];
        o1[0] = make_float4(hi[0],  hi[1],  hi[2],  hi[3]);
        o1[1] = make_float4(hi[4],  hi[5],  hi[6],  hi[7]);
        o1[2] = make_float4(hi[8],  hi[9],  hi[10], hi[11]);
        o1[3] = make_float4(hi[12], hi[13], hi[14], hi[15]);
        o1[4] = make_float4(hi[16], T1, 0.f, 0.f);
    }
}

// -------- 4) combine (16 seg-groups x 32 px) + masked weighted CE + finalize --------
__global__ void __launch_bounds__(LTILE*LGROUPS) k_loss(
    const int* __restrict__ gt, const int* __restrict__ mk,
    const float* __restrict__ cw, float* __restrict__ out)
{
    int cam  = blockIdx.y;
    int t    = threadIdx.x;
    int lane = t & (LTILE-1);         // pixel slot within tile
    int g    = t >> 5;                // segment group 0..15
    int p    = blockIdx.x*LTILE + lane;

    // group g covers segments [start, start+count): 25 = 9*2 + 7*1
    int count = (g < 9) ? 2 : 1;
    int start = (g < 9) ? 2*g : 18 + (g - 9);

    float T = 1.0f;
    float logits[FEAT];
#pragma unroll
    for (int c = 0; c < FEAT; c++) logits[c] = 0.f;
    for (int s = start; s < start + count; s++) {
        int idx = cam*NSEG + s;
        const float4* q = (const float4*)&d_segP[(idx*NPIX + p) * PPW];
        float4 f0 = q[0], f1 = q[1], f2 = q[2], f3 = q[3], f4 = q[4];
        float v[FEAT+1];
        v[0]=f0.x; v[1]=f0.y; v[2]=f0.z; v[3]=f0.w;
        v[4]=f1.x; v[5]=f1.y; v[6]=f1.z; v[7]=f1.w;
        v[8]=f2.x; v[9]=f2.y; v[10]=f2.z; v[11]=f2.w;
        v[12]=f3.x; v[13]=f3.y; v[14]=f3.z; v[15]=f3.w;
        v[16]=f4.x; v[17]=f4.y;   // v[17] = segment T
#pragma unroll
        for (int c = 0; c < FEAT; c++)
            logits[c] = fmaf(T, v[c], logits[c]);
        T *= v[17];
    }

    __shared__ float sA[LGROUPS-1][FEAT][LTILE];
    __shared__ float sT[LGROUPS-1][LTILE];
    if (g > 0) {
#pragma unroll
        for (int c = 0; c < FEAT; c++) sA[g-1][c][lane] = logits[c];
        sT[g-1][lane] = T;
    }
    __syncthreads();

    if (g == 0) {   // warp 0: merge 15 partials, CE, warp reduction
#pragma unroll
        for (int gg = 0; gg < LGROUPS-1; gg++) {
#pragma unroll
            for (int c = 0; c < FEAT; c++)
                logits[c] = fmaf(T, sA[gg][c][lane], logits[c]);
            T *= sT[gg][lane];
        }

        int x = p % RW, y = p / RW;
        int gi = cam*GH*GW + (y*4)*GW + (x*4);
        int gcls = gt[gi];
        float m = (float)mk[gi];

        float mx = logits[0];
#pragma unroll
        for (int c = 1; c < FEAT; c++) mx = fmaxf(mx, logits[c]);
        float se = 0.f;
#pragma unroll
        for (int c = 0; c < FEAT; c++) se += __expf(logits[c] - mx);
        float lg = logits[0];
#pragma unroll
        for (int c = 1; c < FEAT; c++) if (c == gcls) lg = logits[c];
        float nll = -(lg - mx - __logf(se));
        float wi  = cw[gcls] * m;
        float vn = wi * nll, vd = wi;
#pragma unroll
        for (int off = 16; off > 0; off >>= 1) {
            vn += __shfl_down_sync(0xffffffffu, vn, off);
            vd += __shfl_down_sync(0xffffffffu, vd, off);
        }
        if (lane == 0) {
            atomicAdd(&d_num[cam], vn);
            atomicAdd(&d_den[cam], vd);
            __threadfence();
            unsigned int done = atomicAdd(&d_ctr, 1u);
            if (done == LBLOCKS*NCAM - 1) {
                float n0 = atomicAdd(&d_num[0], 0.0f), d0 = atomicAdd(&d_den[0], 0.0f);
                float n1 = atomicAdd(&d_num[1], 0.0f), d1 = atomicAdd(&d_den[1], 0.0f);
                float l0 = n0 / fmaxf(d0, 1e-8f);
                float l1 = n1 / fmaxf(d1, 1e-8f);
                out[0] = 0.5f * (l0 + l1);
            }
        }
    }
}

extern "C" void kernel_launch(void* const* d_in, const int* in_sizes, int n_in,
                              void* d_out, int out_size)
{
    const float* vf  = (const float*)d_in[0];
    const float* op  = (const float*)d_in[1];
    const float* xyz = (const float*)d_in[2];
    const float* sc  = (const float*)d_in[3];
    const float* rt  = (const float*)d_in[4];
    const float* vm  = (const float*)d_in[5];
    const float* in_ = (const float*)d_in[6];
    const float* cw  = (const float*)d_in[7];
    const int*   gt  = (const int*)  d_in[8];
    const int*   mk  = (const int*)  d_in[9];
    float* out = (float*)d_out;

    k_rank  <<<dim3(13, KCH, NCAM), 256>>>(xyz, vm);
    k_ps    <<<dim3(13, NCAM), 256>>>(xyz, sc, rt, op, vm, in_, vf);
    k_render<<<dim3(NSEG, RTILES, NCAM), RBLK>>>();
    k_loss  <<<dim3(LBLOCKS, NCAM), LTILE*LGROUPS>>>(gt, mk, cw, out);
}

// round 16
// speedup vs baseline: 1.0342x; 1.0342x over previous
#include <cuda_runtime.h>

#define N_GAUSS 3200
#define FEAT    17
#define FV4     5             // padded feature float4 count (20 floats)
#define RH      48
#define RW      88
#define NPIX    (RH*RW)       // 4224
#define NPAIR   (NPIX/2)      // 2112
#define NCAM    2
#define GH      192
#define GW      352
#define NSEG    25
#define SEGSZ   128           // 25*128 = 3200
#define KCH     4
#define KLEN    (N_GAUSS/KCH) // 800
#define RTILES  33            // NPAIR/64 render tiling (2 px/thread, 64-thread CTAs)
#define RBLK    64
#define NPAIRCH 9             // (FEAT+1)/2 feature-channel pairs
#define PPW     20            // packed floats per (seg,pixel): 17 logits + T + pad
#define LTILE   32            // pixels per loss CTA
#define LGROUPS 16            // segment groups per loss CTA
#define LBLOCKS (NPIX/LTILE)  // 132 loss CTAs per camera

// -------- device scratch (static: allocation-free) --------
__device__ int    d_rankp[KCH][NCAM*N_GAUSS];  // per-chunk partial ranks (no atomics)
__device__ float4 d_sp0[NCAM*N_GAUSS];   // sorted (v, E, u, op)
__device__ float4 d_sp1[NCAM*N_GAUSS];   // sorted (A, B, C, 0)
__device__ float4 d_sf4[NCAM*NSEG*FV4*SEGSZ]; // sorted feats, seg-blocked
__device__ float  d_segP[NCAM*NSEG*NPIX*PPW]; // packed per-(seg,pixel): 17 logits + T
__device__ float  d_num[NCAM];
__device__ float  d_den[NCAM];
__device__ unsigned int d_ctr;

// deterministic z: explicit fma chain — identical rounding at every call site
__device__ __forceinline__ float zdet(const float* __restrict__ xyz, int k,
                                      float V8, float V9, float V10, float V11)
{
    return __fmaf_rn(V8, xyz[3*k], __fmaf_rn(V9, xyz[3*k+1], __fmaf_rn(V10, xyz[3*k+2], V11)));
}

// -------- 1) stable rank via tiled O(N^2) counting, z computed on the fly --------
__global__ void k_rank(const float* __restrict__ xyz, const float* __restrict__ vm)
{
    int cam = blockIdx.z;
    int ch  = blockIdx.y;
    int n   = blockIdx.x * 256 + threadIdx.x;
    int base = ch * KLEN;
    if (cam == 0 && ch == 0 && blockIdx.x == 0 && threadIdx.x < NCAM) {
        d_num[threadIdx.x] = 0.f; d_den[threadIdx.x] = 0.f;
        if (threadIdx.x == 0) d_ctr = 0u;
    }
    const float* V = vm + cam*16;
    float V8 = V[8], V9 = V[9], V10 = V[10], V11 = V[11];

    __shared__ float tz[256];
    float zn = (n < N_GAUSS) ? zdet(xyz, n, V8, V9, V10, V11) : 0.f;
    int cnt = 0;
    for (int t0 = 0; t0 < KLEN; t0 += 256) {
        int lim = KLEN - t0 < 256 ? KLEN - t0 : 256;
        __syncthreads();
        if (threadIdx.x < lim) tz[threadIdx.x] = zdet(xyz, base + t0 + threadIdx.x, V8, V9, V10, V11);
        __syncthreads();
        if (n < N_GAUSS) {
            for (int j = 0; j < lim; j++) {
                float zm = tz[j];
                int mm = base + t0 + j;
                cnt += (zm < zn) || (zm == zn && mm < n);
            }
        }
    }
    if (n < N_GAUSS) d_rankp[ch][cam*N_GAUSS + n] = cnt;
}

// -------- 2) fused projection (R1 math) + scatter to sorted slots --------
__global__ void k_ps(const float* __restrict__ xyz, const float* __restrict__ scales,
                     const float* __restrict__ rots, const float* __restrict__ opac,
                     const float* __restrict__ vm, const float* __restrict__ intr,
                     const float* __restrict__ feats)
{
    int n = blockIdx.x * 256 + threadIdx.x;
    int cam = blockIdx.y;
    if (n >= N_GAUSS) return;
    int gi = cam*N_GAUSS + n;
    int rank = d_rankp[0][gi] + d_rankp[1][gi] + d_rankp[2][gi] + d_rankp[3][gi];

    const float* V = vm + cam*16;
    float fx = intr[cam*4+0], fy = intr[cam*4+1], cx = intr[cam*4+2], cy = intr[cam*4+3];
    float X = xyz[3*n], Y = xyz[3*n+1], Z = xyz[3*n+2];
    float p0 = V[0]*X + V[1]*Y + V[2] *Z + V[3];
    float p1 = V[4]*X + V[5]*Y + V[6] *Z + V[7];
    float p2 = V[8]*X + V[9]*Y + V[10]*Z + V[11];
    float z  = p2;
    float zc = fmaxf(z, 0.2f);
    float iz = 1.0f / zc;
    float u  = fx*p0*iz + cx;
    float v  = fy*p1*iz + cy;

    float qw = rots[4*n], qx = rots[4*n+1], qy = rots[4*n+2], qz = rots[4*n+3];
    float qn = rsqrtf(qw*qw + qx*qx + qy*qy + qz*qz);
    qw *= qn; qx *= qn; qy *= qn; qz *= qn;
    float R00 = 1.f-2.f*(qy*qy+qz*qz), R01 = 2.f*(qx*qy-qw*qz), R02 = 2.f*(qx*qz+qw*qy);
    float R10 = 2.f*(qx*qy+qw*qz),     R11 = 1.f-2.f*(qx*qx+qz*qz), R12 = 2.f*(qy*qz-qw*qx);
    float R20 = 2.f*(qx*qz-qw*qy),     R21 = 2.f*(qy*qz+qw*qx), R22 = 1.f-2.f*(qx*qx+qy*qy);

    float s0 = __expf(scales[3*n]), s1 = __expf(scales[3*n+1]), s2 = __expf(scales[3*n+2]);
    float e0 = s0*s0, e1 = s1*s1, e2 = s2*s2;

    float M00 = R00*R00*e0 + R01*R01*e1 + R02*R02*e2;
    float M01 = R00*R10*e0 + R01*R11*e1 + R02*R12*e2;
    float M02 = R00*R20*e0 + R01*R21*e1 + R02*R22*e2;
    float M11 = R10*R10*e0 + R11*R11*e1 + R12*R12*e2;
    float M12 = R10*R20*e0 + R11*R21*e1 + R12*R22*e2;
    float M22 = R20*R20*e0 + R21*R21*e1 + R22*R22*e2;

    float W00=V[0],W01=V[1],W02=V[2];
    float W10=V[4],W11=V[5],W12=V[6];
    float W20=V[8],W21=V[9],W22=V[10];
    float T00=W00*M00+W01*M01+W02*M02, T01=W00*M01+W01*M11+W02*M12, T02=W00*M02+W01*M12+W02*M22;
    float T10=W10*M00+W11*M01+W12*M02, T11=W10*M01+W11*M11+W12*M12, T12=W10*M02+W11*M12+W12*M22;
    float T20=W20*M00+W21*M01+W22*M02, T21=W20*M01+W21*M11+W22*M12, T22=W20*M02+W21*M12+W22*M22;
    float C00=T00*W00+T01*W01+T02*W02;
    float C01=T00*W10+T01*W11+T02*W12;
    float C02=T00*W20+T01*W21+T02*W22;
    float C11=T10*W10+T11*W11+T12*W12;
    float C12=T10*W20+T11*W21+T12*W22;
    float C22=T20*W20+T21*W21+T22*W22;

    float fz0 = fx*iz, fz1 = fy*iz;
    float g0 = -fx*p0*iz*iz, g1 = -fy*p1*iz*iz;
    float t0x = C00*fz0 + C02*g0;
    float t0y = C01*fz0 + C12*g0;
    float t0z = C02*fz0 + C22*g0;
    float cov00 = fz0*t0x + g0*t0z;
    float cov01 = fz1*t0y + g1*t0z;
    float t1y = C11*fz1 + C12*g1;
    float t1z = C12*fz1 + C22*g1;
    float cov11 = fz1*t1y + g1*t1z;

    float a = cov00 + 0.3f;
    float b = cov01;
    float c = cov11 + 0.3f;
    float det  = fmaxf(a*c - b*b, 1e-8f);
    float idet = 1.0f / det;

    float oz = (z > 0.2f) ? opac[n] : 0.0f;

    float Ax = c*idet;       // dx^2 coefficient (R1 value)
    float By = -b*idet;      // cross coefficient (R1 value)
    float Cy = a*idet;       // dy^2 coefficient (R1 value)
    float E  = Cy - By*By/Ax;  // 1D marginal coeff: min over dx of -2*pw = E*dy^2

    int pos = cam*N_GAUSS + rank;
    d_sp0[pos] = make_float4(v, E, u, oz);
    d_sp1[pos] = make_float4(Ax, By, Cy, 0.f);

    int seg = rank / SEGSZ, t = rank % SEGSZ;
    const float* f = feats + n*FEAT;
    float fv[FV4*4];
#pragma unroll
    for (int cc = 0; cc < FEAT; cc++) fv[cc] = f[cc];
#pragma unroll
    for (int cc = FEAT; cc < FV4*4; cc++) fv[cc] = 0.f;
    float4* dst = &d_sf4[((cam*NSEG + seg)*FV4)*SEGSZ + t];
#pragma unroll
    for (int j = 0; j < FV4; j++)
        dst[j*SEGSZ] = make_float4(fv[4*j], fv[4*j+1], fv[4*j+2], fv[4*j+3]);
}

// -------- 3) segmented compositing: per-CTA ordered compaction + R13 body --------
__global__ void __launch_bounds__(RBLK) k_render()
{
    int seg  = blockIdx.x;
    int tile = blockIdx.y;
    int cam  = blockIdx.z;
    __shared__ float4 sve[SEGSZ];              // (v, E, u, op)
    __shared__ float4 sab[SEGSZ];              // (A, B, C, 0)
    __shared__ ulonglong2 sfp[NPAIRCH*SEGSZ];  // features duplicated as (f,f) pairs
    __shared__ int  sidx[SEGSZ];               // ordered survivor indices
    __shared__ int  swtot[2];
    __shared__ int  scount;
    int t = threadIdx.x;
#pragma unroll
    for (int tt = t; tt < SEGSZ; tt += RBLK) {
        int g = cam*N_GAUSS + seg*SEGSZ + tt;
        sve[tt] = d_sp0[g];
        sab[tt] = d_sp1[g];
        const float4* src = &d_sf4[((cam*NSEG + seg)*FV4)*SEGSZ + tt];
        float f[FV4*4];
#pragma unroll
        for (int j = 0; j < FV4; j++) {
            float4 q = src[j*SEGSZ];
            f[4*j] = q.x; f[4*j+1] = q.y; f[4*j+2] = q.z; f[4*j+3] = q.w;
        }
#pragma unroll
        for (int j = 0; j < NPAIRCH; j++) {
            ulonglong2 e;
            asm("mov.b64 %0, {%1, %1};" : "=l"(e.x) : "f"(f[2*j]));
            asm("mov.b64 %0, {%1, %1};" : "=l"(e.y) : "f"(f[2*j+1]));
            sfp[j*SEGSZ + t] = e;   // note: tt == t on first pass; loop writes both halves
        }
#pragma unroll
        for (int j = 0; j < NPAIRCH; j++) {
            ulonglong2 e;
            asm("mov.b64 %0, {%1, %1};" : "=l"(e.x) : "f"(f[2*j]));
            asm("mov.b64 %0, {%1, %1};" : "=l"(e.y) : "f"(f[2*j+1]));
            sfp[j*SEGSZ + tt] = e;
        }
    }
    __syncthreads();

    // --- ordered compaction: row-band cull hoisted to CTA level ---
    // CTA covers pixels [pfirst, pfirst+127] -> rows [r_lo, r_hi].
    int pfirst = tile*RBLK*2;
    float r_lo = (float)(pfirst / RW);
    float r_hi = (float)((pfirst + 2*RBLK - 1) / RW);
    {
        int lane = t & 31, wid = t >> 5;
        int g0i = 2*t, g1i = 2*t + 1;
        float4 v0 = sve[g0i], v1 = sve[g1i];
        float dy0 = fmaxf(fmaxf(r_lo - v0.x, v0.x - r_hi), 0.0f);
        float dy1 = fmaxf(fmaxf(r_lo - v1.x, v1.x - r_hi), 0.0f);
        // skip only when for ALL rows in band: -pw >= 0.5*E*dy^2 > 20.5 (> 20 + margin)
        int k0 = !(0.5f*v0.y*dy0*dy0 > 20.5f);
        int k1 = !(0.5f*v1.y*dy1*dy1 > 20.5f);
        int c = k0 + k1;
        int scan = c;
#pragma unroll
        for (int off = 1; off < 32; off <<= 1) {
            int nb = __shfl_up_sync(0xffffffffu, scan, off);
            if (lane >= off) scan += nb;
        }
        if (lane == 31) swtot[wid] = scan;
        __syncthreads();
        int pos = ((wid == 1) ? swtot[0] : 0) + scan - c;
        if (k0) sidx[pos++] = g0i;
        if (k1) sidx[pos]   = g1i;
        if (t == RBLK-1) scount = swtot[0] + swtot[1];
    }
    __syncthreads();

    int pairIdx = tile*RBLK + t;
    int p0 = pairIdx * 2;
    float px0 = (float)(p0 % RW);
    float px1 = px0 + 1.0f;
    float py  = (float)(p0 / RW);
    float T0 = 1.0f, T1 = 1.0f;
    unsigned long long acc2[FEAT+1];
#pragma unroll
    for (int c = 0; c < FEAT+1; c++) acc2[c] = 0ull;

    int cnt = scount;
    for (int j = 0; j < cnt; j++) {
        int i = sidx[j];
        float4 VE = sve[i];            // v, E, u, op
        float4 Q  = sab[i];            // A, B, C
        float dy  = py - VE.x;
        float dx0 = px0 - VE.z;
        float dx1 = px1 - VE.z;
        float pw0 = -0.5f*(Q.x*dx0*dx0 + Q.z*dy*dy) - Q.y*dx0*dy;  // R1 expression
        float pw1 = -0.5f*(Q.x*dx1*dx1 + Q.z*dy*dy) - Q.y*dx1*dy;
        pw0 = fminf(pw0, 0.0f);
        pw1 = fminf(pw1, 0.0f);
        bool s0 = pw0 > -20.0f;
        bool s1 = pw1 > -20.0f;
        if (s0 | s1) {
            float a0 = fminf(VE.w * __expf(pw0), 0.99f);
            float a1 = fminf(VE.w * __expf(pw1), 0.99f);
            float w0 = s0 ? a0 * T0 : 0.0f;
            float w1 = s1 ? a1 * T1 : 0.0f;
            unsigned long long W;
            asm("mov.b64 %0, {%1, %2};" : "=l"(W) : "f"(w0), "f"(w1));
#pragma unroll
            for (int jj = 0; jj < NPAIRCH; jj++) {
                ulonglong2 v = sfp[jj*SEGSZ + i];
                asm("fma.rn.f32x2 %0, %1, %2, %0;" : "+l"(acc2[2*jj])   : "l"(W), "l"(v.x));
                asm("fma.rn.f32x2 %0, %1, %2, %0;" : "+l"(acc2[2*jj+1]) : "l"(W), "l"(v.y));
            }
            if (s0) T0 *= 1.0f - a0;
            if (s1) T1 *= 1.0f - a1;
        }
    }
    {
        int idx = cam*NSEG + seg;
        float lo[FEAT], hi[FEAT];
#pragma unroll
        for (int c = 0; c < FEAT; c++)
            asm("mov.b64 {%0, %1}, %2;" : "=f"(lo[c]), "=f"(hi[c]) : "l"(acc2[c]));
        float4* o0 = (float4*)&d_segP[(idx*NPIX + p0) * PPW];
        o0[0] = make_float4(lo[0],  lo[1],  lo[2],  lo[3]);
        o0[1] = make_float4(lo[4],  lo[5],  lo[6],  lo[7]);
        o0[2] = make_float4(lo[8],  lo[9],  lo[10], lo[11]);
        o0[3] = make_float4(lo[12], lo[13], lo[14], lo[15]);
        o0[4] = make_float4(lo[16], T0, 0.f, 0.f);
        float4* o1 = (float4*)&d_segP[(idx*NPIX + p0 + 1) * PPW];
        o1[0] = make_float4(hi[0],  hi[1],  hi[2],  hi[3]);
        o1[1] = make_float4(hi[4],  hi[5],  hi[6],  hi[7]);
        o1[2] = make_float4(hi[8],  hi[9],  hi[10], hi[11]);
        o1[3] = make_float4(hi[12], hi[13], hi[14], hi[15]);
        o1[4] = make_float4(hi[16], T1, 0.f, 0.f);
    }
}

// -------- 4) combine (16 seg-groups x 32 px) + masked weighted CE + finalize --------
__global__ void __launch_bounds__(LTILE*LGROUPS) k_loss(
    const int* __restrict__ gt, const int* __restrict__ mk,
    const float* __restrict__ cw, float* __restrict__ out)
{
    int cam  = blockIdx.y;
    int t    = threadIdx.x;
    int lane = t & (LTILE-1);         // pixel slot within tile
    int g    = t >> 5;                // segment group 0..15
    int p    = blockIdx.x*LTILE + lane;

    // group g covers segments [start, start+count): 25 = 9*2 + 7*1
    int count = (g < 9) ? 2 : 1;
    int start = (g < 9) ? 2*g : 18 + (g - 9);

    float T = 1.0f;
    float logits[FEAT];
#pragma unroll
    for (int c = 0; c < FEAT; c++) logits[c] = 0.f;
    for (int s = start; s < start + count; s++) {
        int idx = cam*NSEG + s;
        const float4* q = (const float4*)&d_segP[(idx*NPIX + p) * PPW];
        float4 f0 = q[0], f1 = q[1], f2 = q[2], f3 = q[3], f4 = q[4];
        float v[FEAT+1];
        v[0]=f0.x; v[1]=f0.y; v[2]=f0.z; v[3]=f0.w;
        v[4]=f1.x; v[5]=f1.y; v[6]=f1.z; v[7]=f1.w;
        v[8]=f2.x; v[9]=f2.y; v[10]=f2.z; v[11]=f2.w;
        v[12]=f3.x; v[13]=f3.y; v[14]=f3.z; v[15]=f3.w;
        v[16]=f4.x; v[17]=f4.y;   // v[17] = segment T
#pragma unroll
        for (int c = 0; c < FEAT; c++)
            logits[c] = fmaf(T, v[c], logits[c]);
        T *= v[17];
    }

    __shared__ float sA[LGROUPS-1][FEAT][LTILE];
    __shared__ float sT[LGROUPS-1][LTILE];
    if (g > 0) {
#pragma unroll
        for (int c = 0; c < FEAT; c++) sA[g-1][c][lane] = logits[c];
        sT[g-1][lane] = T;
    }
    __syncthreads();

    if (g == 0) {   // warp 0: merge 15 partials, CE, warp reduction
#pragma unroll
        for (int gg = 0; gg < LGROUPS-1; gg++) {
#pragma unroll
            for (int c = 0; c < FEAT; c++)
                logits[c] = fmaf(T, sA[gg][c][lane], logits[c]);
            T *= sT[gg][lane];
        }

        int x = p % RW, y = p / RW;
        int gi = cam*GH*GW + (y*4)*GW + (x*4);
        int gcls = gt[gi];
        float m = (float)mk[gi];

        float mx = logits[0];
#pragma unroll
        for (int c = 1; c < FEAT; c++) mx = fmaxf(mx, logits[c]);
        float se = 0.f;
#pragma unroll
        for (int c = 0; c < FEAT; c++) se += __expf(logits[c] - mx);
        float lg = logits[0];
#pragma unroll
        for (int c = 1; c < FEAT; c++) if (c == gcls) lg = logits[c];
        float nll = -(lg - mx - __logf(se));
        float wi  = cw[gcls] * m;
        float vn = wi * nll, vd = wi;
#pragma unroll
        for (int off = 16; off > 0; off >>= 1) {
            vn += __shfl_down_sync(0xffffffffu, vn, off);
            vd += __shfl_down_sync(0xffffffffu, vd, off);
        }
        if (lane == 0) {
            atomicAdd(&d_num[cam], vn);
            atomicAdd(&d_den[cam], vd);
            __threadfence();
            unsigned int done = atomicAdd(&d_ctr, 1u);
            if (done == LBLOCKS*NCAM - 1) {
                float n0 = atomicAdd(&d_num[0], 0.0f), d0 = atomicAdd(&d_den[0], 0.0f);
                float n1 = atomicAdd(&d_num[1], 0.0f), d1 = atomicAdd(&d_den[1], 0.0f);
                float l0 = n0 / fmaxf(d0, 1e-8f);
                float l1 = n1 / fmaxf(d1, 1e-8f);
                out[0] = 0.5f * (l0 + l1);
            }
        }
    }
}

extern "C" void kernel_launch(void* const* d_in, const int* in_sizes, int n_in,
                              void* d_out, int out_size)
{
    const float* vf  = (const float*)d_in[0];
    const float* op  = (const float*)d_in[1];
    const float* xyz = (const float*)d_in[2];
    const float* sc  = (const float*)d_in[3];
    const float* rt  = (const float*)d_in[4];
    const float* vm  = (const float*)d_in[5];
    const float* in_ = (const float*)d_in[6];
    const float* cw  = (const float*)d_in[7];
    const int*   gt  = (const int*)  d_in[8];
    const int*   mk  = (const int*)  d_in[9];
    float* out = (float*)d_out;

    k_rank  <<<dim3(13, KCH, NCAM), 256>>>(xyz, vm);
    k_ps    <<<dim3(13, NCAM), 256>>>(xyz, sc, rt, op, vm, in_, vf);
    k_render<<<dim3(NSEG, RTILES, NCAM), RBLK>>>();
    k_loss  <<<dim3(LBLOCKS, NCAM), LTILE*LGROUPS>>>(gt, mk, cw, out);
}

// round 17
// speedup vs baseline: 1.1107x; 1.0740x over previous
#include <cuda_runtime.h>

#define N_GAUSS 3200
#define FEAT    17
#define FV4     5             // padded feature float4 count (20 floats)
#define RH      48
#define RW      88
#define NPIX    (RH*RW)       // 4224
#define NPAIR   (NPIX/2)      // 2112
#define NCAM    2
#define GH      192
#define GW      352
#define NSEG    25
#define SEGSZ   128           // 25*128 = 3200
#define KCH     4
#define KLEN    (N_GAUSS/KCH) // 800
#define RTILES  33            // NPAIR/64 render tiling (2 px/thread, 64-thread CTAs)
#define RBLK    64
#define NPAIRCH 9             // (FEAT+1)/2 feature-channel pairs
#define PPW     20            // packed floats per (seg,pixel): 17 logits + T + pad
#define LTILE   16            // pixels per loss CTA
#define LGROUPS 25            // one segment per group
#define LBLOCKS (NPIX/LTILE)  // 264 loss CTAs per camera

// -------- device scratch (static: allocation-free) --------
__device__ int    d_rankp[KCH][NCAM*N_GAUSS];  // per-chunk partial ranks (no atomics)
__device__ float4 d_sp0[NCAM*N_GAUSS];   // sorted u,v,A,B
__device__ float2 d_sp1[NCAM*N_GAUSS];   // sorted C,op
__device__ float4 d_sf4[NCAM*NSEG*FV4*SEGSZ]; // sorted feats, seg-blocked
__device__ float  d_segP[NCAM*NSEG*NPIX*PPW]; // packed per-(seg,pixel): 17 logits + T
__device__ float  d_num[NCAM];
__device__ float  d_den[NCAM];
__device__ unsigned int d_ctr;

// deterministic z: explicit fma chain — identical rounding at every call site
__device__ __forceinline__ float zdet(const float* __restrict__ xyz, int k,
                                      float V8, float V9, float V10, float V11)
{
    return __fmaf_rn(V8, xyz[3*k], __fmaf_rn(V9, xyz[3*k+1], __fmaf_rn(V10, xyz[3*k+2], V11)));
}

// -------- 1) stable rank via tiled O(N^2) counting, z computed on the fly --------
__global__ void k_rank(const float* __restrict__ xyz, const float* __restrict__ vm)
{
    int cam = blockIdx.z;
    int ch  = blockIdx.y;
    int n   = blockIdx.x * 256 + threadIdx.x;
    int base = ch * KLEN;
    if (cam == 0 && ch == 0 && blockIdx.x == 0 && threadIdx.x < NCAM) {
        d_num[threadIdx.x] = 0.f; d_den[threadIdx.x] = 0.f;
        if (threadIdx.x == 0) d_ctr = 0u;
    }
    const float* V = vm + cam*16;
    float V8 = V[8], V9 = V[9], V10 = V[10], V11 = V[11];

    __shared__ float tz[256];
    float zn = (n < N_GAUSS) ? zdet(xyz, n, V8, V9, V10, V11) : 0.f;
    int cnt = 0;
    for (int t0 = 0; t0 < KLEN; t0 += 256) {
        int lim = KLEN - t0 < 256 ? KLEN - t0 : 256;
        __syncthreads();
        if (threadIdx.x < lim) tz[threadIdx.x] = zdet(xyz, base + t0 + threadIdx.x, V8, V9, V10, V11);
        __syncthreads();
        if (n < N_GAUSS) {
            for (int j = 0; j < lim; j++) {
                float zm = tz[j];
                int mm = base + t0 + j;
                cnt += (zm < zn) || (zm == zn && mm < n);
            }
        }
    }
    if (n < N_GAUSS) d_rankp[ch][cam*N_GAUSS + n] = cnt;
}

// -------- 2) fused projection (R1 math) + scatter to sorted slots --------
__global__ void k_ps(const float* __restrict__ xyz, const float* __restrict__ scales,
                     const float* __restrict__ rots, const float* __restrict__ opac,
                     const float* __restrict__ vm, const float* __restrict__ intr,
                     const float* __restrict__ feats)
{
    int n = blockIdx.x * 256 + threadIdx.x;
    int cam = blockIdx.y;
    if (n >= N_GAUSS) return;
    int gi = cam*N_GAUSS + n;
    int rank = d_rankp[0][gi] + d_rankp[1][gi] + d_rankp[2][gi] + d_rankp[3][gi];

    const float* V = vm + cam*16;
    float fx = intr[cam*4+0], fy = intr[cam*4+1], cx = intr[cam*4+2], cy = intr[cam*4+3];
    float X = xyz[3*n], Y = xyz[3*n+1], Z = xyz[3*n+2];
    float p0 = V[0]*X + V[1]*Y + V[2] *Z + V[3];
    float p1 = V[4]*X + V[5]*Y + V[6] *Z + V[7];
    float p2 = V[8]*X + V[9]*Y + V[10]*Z + V[11];
    float z  = p2;
    float zc = fmaxf(z, 0.2f);
    float iz = 1.0f / zc;
    float u  = fx*p0*iz + cx;
    float v  = fy*p1*iz + cy;

    float qw = rots[4*n], qx = rots[4*n+1], qy = rots[4*n+2], qz = rots[4*n+3];
    float qn = rsqrtf(qw*qw + qx*qx + qy*qy + qz*qz);
    qw *= qn; qx *= qn; qy *= qn; qz *= qn;
    float R00 = 1.f-2.f*(qy*qy+qz*qz), R01 = 2.f*(qx*qy-qw*qz), R02 = 2.f*(qx*qz+qw*qy);
    float R10 = 2.f*(qx*qy+qw*qz),     R11 = 1.f-2.f*(qx*qx+qz*qz), R12 = 2.f*(qy*qz-qw*qx);
    float R20 = 2.f*(qx*qz-qw*qy),     R21 = 2.f*(qy*qz+qw*qx), R22 = 1.f-2.f*(qx*qx+qy*qy);

    float s0 = __expf(scales[3*n]), s1 = __expf(scales[3*n+1]), s2 = __expf(scales[3*n+2]);
    float e0 = s0*s0, e1 = s1*s1, e2 = s2*s2;

    float M00 = R00*R00*e0 + R01*R01*e1 + R02*R02*e2;
    float M01 = R00*R10*e0 + R01*R11*e1 + R02*R12*e2;
    float M02 = R00*R20*e0 + R01*R21*e1 + R02*R22*e2;
    float M11 = R10*R10*e0 + R11*R11*e1 + R12*R12*e2;
    float M12 = R10*R20*e0 + R11*R21*e1 + R12*R22*e2;
    float M22 = R20*R20*e0 + R21*R21*e1 + R22*R22*e2;

    float W00=V[0],W01=V[1],W02=V[2];
    float W10=V[4],W11=V[5],W12=V[6];
    float W20=V[8],W21=V[9],W22=V[10];
    float T00=W00*M00+W01*M01+W02*M02, T01=W00*M01+W01*M11+W02*M12, T02=W00*M02+W01*M12+W02*M22;
    float T10=W10*M00+W11*M01+W12*M02, T11=W10*M01+W11*M11+W12*M12, T12=W10*M02+W11*M12+W12*M22;
    float T20=W20*M00+W21*M01+W22*M02, T21=W20*M01+W21*M11+W22*M12, T22=W20*M02+W21*M12+W22*M22;
    float C00=T00*W00+T01*W01+T02*W02;
    float C01=T00*W10+T01*W11+T02*W12;
    float C02=T00*W20+T01*W21+T02*W22;
    float C11=T10*W10+T11*W11+T12*W12;
    float C12=T10*W20+T11*W21+T12*W22;
    float C22=T20*W20+T21*W21+T22*W22;

    float fz0 = fx*iz, fz1 = fy*iz;
    float g0 = -fx*p0*iz*iz, g1 = -fy*p1*iz*iz;
    float t0x = C00*fz0 + C02*g0;
    float t0y = C01*fz0 + C12*g0;
    float t0z = C02*fz0 + C22*g0;
    float cov00 = fz0*t0x + g0*t0z;
    float cov01 = fz1*t0y + g1*t0z;
    float t1y = C11*fz1 + C12*g1;
    float t1z = C12*fz1 + C22*g1;
    float cov11 = fz1*t1y + g1*t1z;

    float a = cov00 + 0.3f;
    float b = cov01;
    float c = cov11 + 0.3f;
    float det  = fmaxf(a*c - b*b, 1e-8f);
    float idet = 1.0f / det;

    float oz = (z > 0.2f) ? opac[n] : 0.0f;

    int pos = cam*N_GAUSS + rank;
    d_sp0[pos] = make_float4(u, v, c*idet, -b*idet);
    d_sp1[pos] = make_float2(a*idet, oz);

    int seg = rank / SEGSZ, t = rank % SEGSZ;
    const float* f = feats + n*FEAT;
    float fv[FV4*4];
#pragma unroll
    for (int cc = 0; cc < FEAT; cc++) fv[cc] = f[cc];
#pragma unroll
    for (int cc = FEAT; cc < FV4*4; cc++) fv[cc] = 0.f;
    float4* dst = &d_sf4[((cam*NSEG + seg)*FV4)*SEGSZ + t];
#pragma unroll
    for (int j = 0; j < FV4; j++)
        dst[j*SEGSZ] = make_float4(fv[4*j], fv[4*j+1], fv[4*j+2], fv[4*j+3]);
}

// -------- 3) segmented compositing: 2 px/thread + FFMA2, packed epilogue (R13) --------
__global__ void __launch_bounds__(RBLK) k_render()
{
    int seg  = blockIdx.x;
    int tile = blockIdx.y;
    int cam  = blockIdx.z;
    __shared__ float4 sp0[SEGSZ];
    __shared__ float2 sp1[SEGSZ];
    __shared__ ulonglong2 sfp[NPAIRCH*SEGSZ];  // features duplicated as (f,f) pairs
    int t = threadIdx.x;
#pragma unroll
    for (int tt = t; tt < SEGSZ; tt += RBLK) {
        int g = cam*N_GAUSS + seg*SEGSZ + tt;
        sp0[tt] = d_sp0[g];
        sp1[tt] = d_sp1[g];
        const float4* src = &d_sf4[((cam*NSEG + seg)*FV4)*SEGSZ + tt];
        float f[FV4*4];
#pragma unroll
        for (int j = 0; j < FV4; j++) {
            float4 q = src[j*SEGSZ];
            f[4*j] = q.x; f[4*j+1] = q.y; f[4*j+2] = q.z; f[4*j+3] = q.w;
        }
#pragma unroll
        for (int j = 0; j < NPAIRCH; j++) {
            ulonglong2 e;
            asm("mov.b64 %0, {%1, %1};" : "=l"(e.x) : "f"(f[2*j]));
            asm("mov.b64 %0, {%1, %1};" : "=l"(e.y) : "f"(f[2*j+1]));
            sfp[j*SEGSZ + tt] = e;
        }
    }
    __syncthreads();

    int pairIdx = tile*RBLK + t;
    int p0 = pairIdx * 2;
    float px0 = (float)(p0 % RW);
    float px1 = px0 + 1.0f;
    float py  = (float)(p0 / RW);
    float T0 = 1.0f, T1 = 1.0f;
    unsigned long long acc2[FEAT+1];
#pragma unroll
    for (int c = 0; c < FEAT+1; c++) acc2[c] = 0ull;

#pragma unroll 2
    for (int i = 0; i < SEGSZ; i++) {
        float4 P = sp0[i];
        float2 Q = sp1[i];
        float dy  = py - P.y;
        float dx0 = px0 - P.x;
        float dx1 = px1 - P.x;
        float pw0 = -0.5f*(P.z*dx0*dx0 + Q.x*dy*dy) - P.w*dx0*dy;  // R1 expression
        float pw1 = -0.5f*(P.z*dx1*dx1 + Q.x*dy*dy) - P.w*dx1*dy;
        pw0 = fminf(pw0, 0.0f);
        pw1 = fminf(pw1, 0.0f);
        bool s0 = pw0 > -20.0f;
        bool s1 = pw1 > -20.0f;
        if (s0 | s1) {
            float a0 = fminf(Q.y * __expf(pw0), 0.99f);
            float a1 = fminf(Q.y * __expf(pw1), 0.99f);
            float w0 = s0 ? a0 * T0 : 0.0f;
            float w1 = s1 ? a1 * T1 : 0.0f;
            unsigned long long W;
            asm("mov.b64 %0, {%1, %2};" : "=l"(W) : "f"(w0), "f"(w1));
#pragma unroll
            for (int j = 0; j < NPAIRCH; j++) {
                ulonglong2 v = sfp[j*SEGSZ + i];
                asm("fma.rn.f32x2 %0, %1, %2, %0;" : "+l"(acc2[2*j])   : "l"(W), "l"(v.x));
                asm("fma.rn.f32x2 %0, %1, %2, %0;" : "+l"(acc2[2*j+1]) : "l"(W), "l"(v.y));
            }
            if (s0) T0 *= 1.0f - a0;
            if (s1) T1 *= 1.0f - a1;
        }
    }
    {
        int idx = cam*NSEG + seg;
        float lo[FEAT], hi[FEAT];
#pragma unroll
        for (int c = 0; c < FEAT; c++)
            asm("mov.b64 {%0, %1}, %2;" : "=f"(lo[c]), "=f"(hi[c]) : "l"(acc2[c]));
        float4* o0 = (float4*)&d_segP[(idx*NPIX + p0) * PPW];
        o0[0] = make_float4(lo[0],  lo[1],  lo[2],  lo[3]);
        o0[1] = make_float4(lo[4],  lo[5],  lo[6],  lo[7]);
        o0[2] = make_float4(lo[8],  lo[9],  lo[10], lo[11]);
        o0[3] = make_float4(lo[12], lo[13], lo[14], lo[15]);
        o0[4] = make_float4(lo[16], T0, 0.f, 0.f);
        float4* o1 = (float4*)&d_segP[(idx*NPIX + p0 + 1) * PPW];
        o1[0] = make_float4(hi[0],  hi[1],  hi[2],  hi[3]);
        o1[1] = make_float4(hi[4],  hi[5],  hi[6],  hi[7]);
        o1[2] = make_float4(hi[8],  hi[9],  hi[10], hi[11]);
        o1[3] = make_float4(hi[12], hi[13], hi[14], hi[15]);
        o1[4] = make_float4(hi[16], T1, 0.f, 0.f);
    }
}

// -------- 4) combine (25 seg-groups x 16 px) + masked weighted CE + finalize --------
__global__ void __launch_bounds__(LTILE*LGROUPS) k_loss(
    const int* __restrict__ gt, const int* __restrict__ mk,
    const float* __restrict__ cw, float* __restrict__ out)
{
    int cam  = blockIdx.y;
    int t    = threadIdx.x;
    int lane = t & (LTILE-1);         // pixel slot within tile (0..15)
    int g    = t >> 4;                // segment group 0..24 (= segment index)
    int p    = blockIdx.x*LTILE + lane;

    // each group loads exactly one segment: fully parallel, zero serial chain
    float logits[FEAT];
    float T;
    {
        int idx = cam*NSEG + g;
        const float4* q = (const float4*)&d_segP[(idx*NPIX + p) * PPW];
        float4 f0 = q[0], f1 = q[1], f2 = q[2], f3 = q[3], f4 = q[4];
        logits[0]=f0.x; logits[1]=f0.y; logits[2]=f0.z; logits[3]=f0.w;
        logits[4]=f1.x; logits[5]=f1.y; logits[6]=f1.z; logits[7]=f1.w;
        logits[8]=f2.x; logits[9]=f2.y; logits[10]=f2.z; logits[11]=f2.w;
        logits[12]=f3.x; logits[13]=f3.y; logits[14]=f3.z; logits[15]=f3.w;
        logits[16]=f4.x; T = f4.y;
    }

    __shared__ float sA[LGROUPS-1][FEAT][LTILE];
    __shared__ float sT[LGROUPS-1][LTILE];
    if (g > 0) {
#pragma unroll
        for (int c = 0; c < FEAT; c++) sA[g-1][c][lane] = logits[c];
        sT[g-1][lane] = T;
    }
    __syncthreads();

    if (g == 0) {   // threads 0..15 (warp 0): merge 24 partials in order, CE, reduce
#pragma unroll
        for (int gg = 0; gg < LGROUPS-1; gg++) {
#pragma unroll
            for (int c = 0; c < FEAT; c++)
                logits[c] = fmaf(T, sA[gg][c][lane], logits[c]);
            T *= sT[gg][lane];
        }

        int x = p % RW, y = p / RW;
        int gi = cam*GH*GW + (y*4)*GW + (x*4);
        int gcls = gt[gi];
        float m = (float)mk[gi];

        float mx = logits[0];
#pragma unroll
        for (int c = 1; c < FEAT; c++) mx = fmaxf(mx, logits[c]);
        float se = 0.f;
#pragma unroll
        for (int c = 0; c < FEAT; c++) se += __expf(logits[c] - mx);
        float lg = logits[0];
#pragma unroll
        for (int c = 1; c < FEAT; c++) if (c == gcls) lg = logits[c];
        float nll = -(lg - mx - __logf(se));
        float wi  = cw[gcls] * m;
        float vn = wi * nll, vd = wi;
#pragma unroll
        for (int off = 8; off > 0; off >>= 1) {
            vn += __shfl_down_sync(0x0000ffffu, vn, off, 16);
            vd += __shfl_down_sync(0x0000ffffu, vd, off, 16);
        }
        if (lane == 0) {
            atomicAdd(&d_num[cam], vn);
            atomicAdd(&d_den[cam], vd);
            __threadfence();
            unsigned int done = atomicAdd(&d_ctr, 1u);
            if (done == LBLOCKS*NCAM - 1) {
                float n0 = atomicAdd(&d_num[0], 0.0f), d0 = atomicAdd(&d_den[0], 0.0f);
                float n1 = atomicAdd(&d_num[1], 0.0f), d1 = atomicAdd(&d_den[1], 0.0f);
                float l0 = n0 / fmaxf(d0, 1e-8f);
                float l1 = n1 / fmaxf(d1, 1e-8f);
                out[0] = 0.5f * (l0 + l1);
            }
        }
    }
}

extern "C" void kernel_launch(void* const* d_in, const int* in_sizes, int n_in,
                              void* d_out, int out_size)
{
    const float* vf  = (const float*)d_in[0];
    const float* op  = (const float*)d_in[1];
    const float* xyz = (const float*)d_in[2];
    const float* sc  = (const float*)d_in[3];
    const float* rt  = (const float*)d_in[4];
    const float* vm  = (const float*)d_in[5];
    const float* in_ = (const float*)d_in[6];
    const float* cw  = (const float*)d_in[7];
    const int*   gt  = (const int*)  d_in[8];
    const int*   mk  = (const int*)  d_in[9];
    float* out = (float*)d_out;

    k_rank  <<<dim3(13, KCH, NCAM), 256>>>(xyz, vm);
    k_ps    <<<dim3(13, NCAM), 256>>>(xyz, sc, rt, op, vm, in_, vf);
    k_render<<<dim3(NSEG, RTILES, NCAM), RBLK>>>();
    k_loss  <<<dim3(LBLOCKS, NCAM), LTILE*LGROUPS>>>(gt, mk, cw, out);
}